// round 12
// baseline (speedup 1.0000x reference)
#include <cuda_runtime.h>
#include <cstdint>

// Two-pass RNN.  h_t = tanh( xproj[t] + h_{t-1} @ W_hh^T ),  out = h_{T-1}
// B=4096, T=512, IN=15, HID=20.
//
// R10/R11 ncu showed the binder is the MIO/L1tex wavefront pipe moving 35
// operands/lane/step (LDS or SHFL alike). Fix: hoist the non-recurrent
// x-projection into a parallel pass-1 writing xproj pairs to GMEM scratch in
// [t][b][pair] layout (coalesced 240B/warp). Pass-2's recurrence then needs
// only a PRIVATE LDG.64 per lane (no exchange) + the 20-float h vector
// (1 STS.64 + 5 LDS.128 = ~21 wf/warp-step, down from ~39).
// Warp = 3 batches x 10 lanes; lane owns units 2tl,2tl+1. MUFU.TANH.

#define T_STEPS 512
#define BATCH   4096
#define N_IN    15
#define N_HID   20
#define BPW     3
#define THREADS 32
#define N_CTAS  ((BATCH + BPW - 1) / BPW)   // 1366
#define FULL    0xffffffffu

typedef unsigned long long ull;

// 512 * 4096 * 10 pairs * 8B = 167,772,160 B scratch (zero-init bss)
__device__ ull g_xproj[T_STEPS][BATCH][10];

__device__ __forceinline__ ull pack2(float lo, float hi) {
    ull r; asm("mov.b64 %0, {%1, %2};" : "=l"(r) : "f"(lo), "f"(hi)); return r;
}
__device__ __forceinline__ ull fma2(ull a, ull b, ull c) {
    ull d; asm("fma.rn.f32x2 %0, %1, %2, %3;" : "=l"(d) : "l"(a), "l"(b), "l"(c)); return d;
}
__device__ __forceinline__ ull add2(ull a, ull b) {
    ull d; asm("add.rn.f32x2 %0, %1, %2;" : "=l"(d) : "l"(a), "l"(b)); return d;
}
__device__ __forceinline__ float hsum2(ull a) {
    float lo, hi; asm("mov.b64 {%0, %1}, %2;" : "=f"(lo), "=f"(hi) : "l"(a));
    return lo + hi;
}
__device__ __forceinline__ void unpack2(ull a, float& lo, float& hi) {
    asm("mov.b64 {%0, %1}, %2;" : "=f"(lo), "=f"(hi) : "l"(a));
}
__device__ __forceinline__ float tanh_mufu(float z) {
    float r; asm("tanh.approx.f32 %0, %1;" : "=f"(r) : "f"(z)); return r;
}

// ---------------- Pass 1: xproj[t][b][tl] = (z_{2tl}, z_{2tl+1}) ----------
// R10's proven x-staging structure (smem double buffer + dist-3 LDG FIFO).
__global__ __launch_bounds__(THREADS, 10)
void rnn_xproj_kernel(const float* __restrict__ feature,
                      const float* __restrict__ W_ih,
                      const float* __restrict__ b_ih,
                      const float* __restrict__ b_hh)
{
    __shared__ __align__(16) float xs[2][BPW][16];

    const int lane = threadIdx.x & 31;
    const int g    = lane / 10;
    const int tl   = lane % 10;
    const bool active = (g < BPW);
    const int  gc  = active ? g : 0;
    const int  b   = blockIdx.x * BPW + gc;
    const bool valid = active && (b < BATCH);
    const int j0 = 2 * tl, j1 = 2 * tl + 1;

    ull wx0[8], wx1[8];
#pragma unroll
    for (int p = 0; p < 7; p++) {
        wx0[p] = pack2(W_ih[j0 * N_IN + 2 * p], W_ih[j0 * N_IN + 2 * p + 1]);
        wx1[p] = pack2(W_ih[j1 * N_IN + 2 * p], W_ih[j1 * N_IN + 2 * p + 1]);
    }
    wx0[7] = pack2(W_ih[j0 * N_IN + 14], 0.0f);
    wx1[7] = pack2(W_ih[j1 * N_IN + 14], 0.0f);
    const ull bias2_0 = pack2(b_ih[j0] + b_hh[j0], 0.0f);
    const ull bias2_1 = pack2(b_ih[j1] + b_hh[j1], 0.0f);

    const float* xrow = feature + (size_t)(valid ? b : 0) * T_STEPS * N_IN;
    if (valid) {
        xs[0][gc][tl] = xrow[tl];
        if (tl < 5) xs[0][gc][10 + tl] = xrow[10 + tl];
        if (tl == 0) { xs[0][gc][15] = 0.0f; xs[1][gc][15] = 0.0f; }
    }
    float fa1 = valid ? xrow[1 * N_IN + tl] : 0.0f;
    float fb1 = (valid && tl < 5) ? xrow[1 * N_IN + 10 + tl] : 0.0f;
    float fa2 = valid ? xrow[2 * N_IN + tl] : 0.0f;
    float fb2 = (valid && tl < 5) ? xrow[2 * N_IN + 10 + tl] : 0.0f;
    float fa3 = valid ? xrow[3 * N_IN + tl] : 0.0f;
    float fb3 = (valid && tl < 5) ? xrow[3 * N_IN + 10 + tl] : 0.0f;

#pragma unroll 2
    for (int t = 0; t < T_STEPS; t++) {
        const int p = t & 1;
        __syncwarp();

        if (valid) {
            xs[p ^ 1][gc][tl] = fa1;
            if (tl < 5) xs[p ^ 1][gc][10 + tl] = fb1;
        }
        fa1 = fa2; fb1 = fb2;
        fa2 = fa3; fb2 = fb3;
        if (valid && (t + 4) < T_STEPS) {
            fa3 = xrow[(t + 4) * N_IN + tl];
            fb3 = (tl < 5) ? xrow[(t + 4) * N_IN + 10 + tl] : 0.0f;
        } else { fa3 = 0.0f; fb3 = 0.0f; }

        ull xp[8];
        {
            const ulonglong2* xv = (const ulonglong2*)xs[p][gc];
            ulonglong2 v0 = xv[0], v1 = xv[1], v2 = xv[2], v3 = xv[3];
            xp[0] = v0.x; xp[1] = v0.y; xp[2] = v1.x; xp[3] = v1.y;
            xp[4] = v2.x; xp[5] = v2.y; xp[6] = v3.x; xp[7] = v3.y;
        }

        ull a0 = bias2_0, c0 = 0ull, a1 = bias2_1, c1 = 0ull;
#pragma unroll
        for (int k = 0; k < 8; k++) {
            if (k & 1) { c0 = fma2(xp[k], wx0[k], c0); c1 = fma2(xp[k], wx1[k], c1); }
            else       { a0 = fma2(xp[k], wx0[k], a0); a1 = fma2(xp[k], wx1[k], a1); }
        }
        const float z0 = hsum2(add2(a0, c0));
        const float z1 = hsum2(add2(a1, c1));

        if (valid) g_xproj[t][b][tl] = pack2(z0, z1);  // 240B/warp, coalesced
    }
}

// ---------------- Pass 2: the lean recurrence ------------------------------
__global__ __launch_bounds__(THREADS, 10)
void rnn_recur_kernel(const float* __restrict__ W_hh,
                      float* __restrict__ out)
{
    // h pairs, double buffered: [phase][batch-slot][pair]; rows 80B (16B mult.)
    __shared__ __align__(16) ull hsm[2][BPW][10];

    const int lane = threadIdx.x & 31;
    const int g    = lane / 10;
    const int tl   = lane % 10;
    const bool active = (g < BPW);
    const int  gc  = active ? g : 0;
    const int  b   = blockIdx.x * BPW + gc;
    const bool valid = active && (b < BATCH);
    const int  bld = valid ? b : (BATCH - 1);    // clamped for safe loads
    const int j0 = 2 * tl, j1 = 2 * tl + 1;

    ull wh0[10], wh1[10];
#pragma unroll
    for (int p = 0; p < 10; p++) {
        wh0[p] = pack2(W_hh[j0 * N_HID + 2 * p], W_hh[j0 * N_HID + 2 * p + 1]);
        wh1[p] = pack2(W_hh[j1 * N_HID + 2 * p], W_hh[j1 * N_HID + 2 * p + 1]);
    }

    // h_{-1} = 0
    if (active) hsm[0][gc][tl] = 0ull;

    // private xproj FIFO (distance 3): cur=t, f1..f3 = t+1..t+3
    ull cur = g_xproj[0][bld][tl];
    ull f1  = g_xproj[1][bld][tl];
    ull f2  = g_xproj[2][bld][tl];
    ull f3  = g_xproj[3][bld][tl];

    ull hpk = 0ull;

#pragma unroll 2
    for (int t = 0; t < T_STEPS; t++) {
        const int p = t & 1;
        __syncwarp();   // prev STS(buf p) visible; prev readers of p^1 done

        // gather h_{t-1}: 5x LDS.128 (the only exchange in this kernel)
        ull hp[10];
        {
            const ulonglong2* hv = (const ulonglong2*)hsm[p][gc];
            ulonglong2 v0 = hv[0], v1 = hv[1], v2 = hv[2], v3 = hv[3], v4 = hv[4];
            hp[0] = v0.x; hp[1] = v0.y; hp[2] = v1.x; hp[3] = v1.y;
            hp[4] = v2.x; hp[5] = v2.y; hp[6] = v3.x; hp[7] = v3.y;
            hp[8] = v4.x; hp[9] = v4.y;
        }

        // split private xproj pair into chain inits
        float x0, x1; unpack2(cur, x0, x1);
        // rotate FIFO; prefetch xproj[t+4]
        cur = f1; f1 = f2; f2 = f3;
        f3 = ((t + 4) < T_STEPS) ? g_xproj[t + 4][bld][tl] : 0ull;

        // 20 fma2 over 4 chains (depth 5)
        ull a0 = pack2(x0, 0.0f), c0 = 0ull;
        ull a1 = pack2(x1, 0.0f), c1 = 0ull;
#pragma unroll
        for (int k = 0; k < 10; k++) {
            if (k & 1) { c0 = fma2(hp[k], wh0[k], c0); c1 = fma2(hp[k], wh1[k], c1); }
            else       { a0 = fma2(hp[k], wh0[k], a0); a1 = fma2(hp[k], wh1[k], a1); }
        }
        const float z0 = hsum2(add2(a0, c0));
        const float z1 = hsum2(add2(a1, c1));

        hpk = pack2(tanh_mufu(z0), tanh_mufu(z1));

        if (active) hsm[p ^ 1][gc][tl] = hpk;   // STS.64
    }

    if (valid) {
        float lo, hi; unpack2(hpk, lo, hi);
        *(float2*)&out[b * N_HID + j0] = make_float2(lo, hi);
    }
}

extern "C" void kernel_launch(void* const* d_in, const int* in_sizes, int n_in,
                              void* d_out, int out_size)
{
    const float* feature = (const float*)d_in[0];
    const float* W_ih    = (const float*)d_in[1];
    const float* W_hh    = (const float*)d_in[2];
    const float* b_ih    = (const float*)d_in[3];
    const float* b_hh    = (const float*)d_in[4];
    float* out = (float*)d_out;

    rnn_xproj_kernel<<<N_CTAS, THREADS>>>(feature, W_ih, b_ih, b_hh);
    rnn_recur_kernel<<<N_CTAS, THREADS>>>(W_hh, out);
}

// round 13
// speedup vs baseline: 1.7264x; 1.7264x over previous
#include <cuda_runtime.h>
#include <cstdint>

// Two-pass RNN.  h_t = tanh( xproj[t] + h_{t-1} @ W_hh^T ),  out = h_{T-1}
// B=4096, T=512, IN=15, HID=20.
//
// R12 ncu (pass2: L1 22.7%, issue 18.2%, ~575cyc/step with nothing busy)
// exposed the real binder of R9-R12: the register-FIFO ROTATION (f2=f3)
// reads the LDG destination one step after issue -> effective prefetch
// distance 1 (~150cyc) vs DRAM 577cyc -> ~430cyc long_scoreboard per step.
// Fix: 4-slot FIFO indexed by (t&3) under unroll 4 — value loaded at step t
// is first read at t+4 (>=577cyc cover), no inter-slot register moves.
// Pass-1: shfl-distributed x (no smem/sync, steps independent, BW-bound).
// Pass-2: lean recurrence, private xproj LDG.64 + h via warp-local smem.

#define T_STEPS 512
#define BATCH   4096
#define N_IN    15
#define N_HID   20
#define BPW     3
#define THREADS 32
#define N_CTAS  ((BATCH + BPW - 1) / BPW)   // 1366
#define FULL    0xffffffffu

typedef unsigned long long ull;

// 512 * 4096 * 10 pairs * 8B = 167,772,160 B scratch
__device__ ull g_xproj[T_STEPS][BATCH][10];

__device__ __forceinline__ ull pack2(float lo, float hi) {
    ull r; asm("mov.b64 %0, {%1, %2};" : "=l"(r) : "f"(lo), "f"(hi)); return r;
}
__device__ __forceinline__ ull fma2(ull a, ull b, ull c) {
    ull d; asm("fma.rn.f32x2 %0, %1, %2, %3;" : "=l"(d) : "l"(a), "l"(b), "l"(c)); return d;
}
__device__ __forceinline__ ull add2(ull a, ull b) {
    ull d; asm("add.rn.f32x2 %0, %1, %2;" : "=l"(d) : "l"(a), "l"(b)); return d;
}
__device__ __forceinline__ float hsum2(ull a) {
    float lo, hi; asm("mov.b64 {%0, %1}, %2;" : "=f"(lo), "=f"(hi) : "l"(a));
    return lo + hi;
}
__device__ __forceinline__ void unpack2(ull a, float& lo, float& hi) {
    asm("mov.b64 {%0, %1}, %2;" : "=f"(lo), "=f"(hi) : "l"(a));
}
__device__ __forceinline__ float tanh_mufu(float z) {
    float r; asm("tanh.approx.f32 %0, %1;" : "=f"(r) : "f"(z)); return r;
}

// ---------------- Pass 1: xproj[t][b][tl] = (z_{2tl}, z_{2tl+1}) -----------
// Steps independent -> pure throughput. Loader lane tl<8 holds packed x-pair
// slot; consumers shfl64 at use time. No smem, no syncwarp.
__global__ __launch_bounds__(THREADS, 10)
void rnn_xproj_kernel(const float* __restrict__ feature,
                      const float* __restrict__ W_ih,
                      const float* __restrict__ b_ih,
                      const float* __restrict__ b_hh)
{
    const int lane = threadIdx.x & 31;
    const int g    = lane / 10;
    const int tl   = lane % 10;
    const bool active = (g < BPW);
    const int  gc  = active ? g : 0;
    const int  base = gc * 10;
    const int  b   = blockIdx.x * BPW + gc;
    const bool valid = active && (b < BATCH);
    const int j0 = 2 * tl, j1 = 2 * tl + 1;

    const bool xl  = valid && (tl < 8);     // loader of pair (x[2tl], x[2tl+1])
    const bool xhi = (tl < 7);              // pair 7 = (x14, 0)

    ull wx0[8], wx1[8];
#pragma unroll
    for (int p = 0; p < 7; p++) {
        wx0[p] = pack2(W_ih[j0 * N_IN + 2 * p], W_ih[j0 * N_IN + 2 * p + 1]);
        wx1[p] = pack2(W_ih[j1 * N_IN + 2 * p], W_ih[j1 * N_IN + 2 * p + 1]);
    }
    wx0[7] = pack2(W_ih[j0 * N_IN + 14], 0.0f);
    wx1[7] = pack2(W_ih[j1 * N_IN + 14], 0.0f);
    const ull bias2_0 = pack2(b_ih[j0] + b_hh[j0], 0.0f);
    const ull bias2_1 = pack2(b_ih[j1] + b_hh[j1], 0.0f);

    const float* xrow = feature + (size_t)(valid ? b : 0) * T_STEPS * N_IN;

    // 4-slot FIFO, statically indexed: slot q holds x_t pair with t&3==q.
    ull fx[4];
#pragma unroll
    for (int q = 0; q < 4; q++)
        fx[q] = xl ? pack2(xrow[q * N_IN + 2 * tl],
                           xhi ? xrow[q * N_IN + 2 * tl + 1] : 0.0f) : 0ull;

#pragma unroll 4
    for (int t = 0; t < T_STEPS; t++) {
        const int q = t & 3;

        // distribute x_t pairs from loader lanes (reads slot q THIS step...)
        ull xp[8];
#pragma unroll
        for (int p = 0; p < 8; p++)
            xp[p] = __shfl_sync(FULL, fx[q], base + p);

        // ...then refill slot q for t+4 (first read again at t+4: full cover)
        if (xl && (t + 4) < T_STEPS) {
            const float* r4 = xrow + (t + 4) * N_IN + 2 * tl;
            fx[q] = pack2(r4[0], xhi ? r4[1] : 0.0f);
        }

        ull a0 = bias2_0, c0 = 0ull, a1 = bias2_1, c1 = 0ull;
#pragma unroll
        for (int k = 0; k < 8; k++) {
            if (k & 1) { c0 = fma2(xp[k], wx0[k], c0); c1 = fma2(xp[k], wx1[k], c1); }
            else       { a0 = fma2(xp[k], wx0[k], a0); a1 = fma2(xp[k], wx1[k], a1); }
        }
        const float z0 = hsum2(add2(a0, c0));
        const float z1 = hsum2(add2(a1, c1));

        if (valid) g_xproj[t][b][tl] = pack2(z0, z1);  // 240B/warp coalesced
    }
}

// ---------------- Pass 2: the lean recurrence ------------------------------
__global__ __launch_bounds__(THREADS, 10)
void rnn_recur_kernel(const float* __restrict__ W_hh,
                      float* __restrict__ out)
{
    __shared__ __align__(16) ull hsm[2][BPW][10];   // h pairs, double buffered

    const int lane = threadIdx.x & 31;
    const int g    = lane / 10;
    const int tl   = lane % 10;
    const bool active = (g < BPW);
    const int  gc  = active ? g : 0;
    const int  b   = blockIdx.x * BPW + gc;
    const bool valid = active && (b < BATCH);
    const int  bld = valid ? b : (BATCH - 1);
    const int j0 = 2 * tl, j1 = 2 * tl + 1;

    ull wh0[10], wh1[10];
#pragma unroll
    for (int p = 0; p < 10; p++) {
        wh0[p] = pack2(W_hh[j0 * N_HID + 2 * p], W_hh[j0 * N_HID + 2 * p + 1]);
        wh1[p] = pack2(W_hh[j1 * N_HID + 2 * p], W_hh[j1 * N_HID + 2 * p + 1]);
    }

    if (active) hsm[0][gc][tl] = 0ull;   // h_{-1} = 0

    // 4-slot xproj FIFO, statically indexed (distance-4 cover, no rotation)
    ull fx[4];
#pragma unroll
    for (int q = 0; q < 4; q++)
        fx[q] = g_xproj[q][bld][tl];

    ull hpk = 0ull;

#pragma unroll 4
    for (int t = 0; t < T_STEPS; t++) {
        const int p = t & 1;
        const int q = t & 3;
        __syncwarp();   // prev STS(buf p) visible; prev readers of p^1 done

        // gather h_{t-1}: 5x LDS.128 (only exchange in this kernel)
        ull hp[10];
        {
            const ulonglong2* hv = (const ulonglong2*)hsm[p][gc];
            ulonglong2 v0 = hv[0], v1 = hv[1], v2 = hv[2], v3 = hv[3], v4 = hv[4];
            hp[0] = v0.x; hp[1] = v0.y; hp[2] = v1.x; hp[3] = v1.y;
            hp[4] = v2.x; hp[5] = v2.y; hp[6] = v3.x; hp[7] = v3.y;
            hp[8] = v4.x; hp[9] = v4.y;
        }

        // consume slot q (loaded at t-4), then refill for t+4
        float x0, x1; unpack2(fx[q], x0, x1);
        if ((t + 4) < T_STEPS) fx[q] = g_xproj[t + 4][bld][tl];

        // 20 fma2 over 4 chains (depth 5)
        ull a0 = pack2(x0, 0.0f), c0 = 0ull;
        ull a1 = pack2(x1, 0.0f), c1 = 0ull;
#pragma unroll
        for (int k = 0; k < 10; k++) {
            if (k & 1) { c0 = fma2(hp[k], wh0[k], c0); c1 = fma2(hp[k], wh1[k], c1); }
            else       { a0 = fma2(hp[k], wh0[k], a0); a1 = fma2(hp[k], wh1[k], a1); }
        }
        const float z0 = hsum2(add2(a0, c0));
        const float z1 = hsum2(add2(a1, c1));

        hpk = pack2(tanh_mufu(z0), tanh_mufu(z1));

        if (active) hsm[p ^ 1][gc][tl] = hpk;   // STS.64
    }

    if (valid) {
        float lo, hi; unpack2(hpk, lo, hi);
        *(float2*)&out[b * N_HID + j0] = make_float2(lo, hi);
    }
}

extern "C" void kernel_launch(void* const* d_in, const int* in_sizes, int n_in,
                              void* d_out, int out_size)
{
    const float* feature = (const float*)d_in[0];
    const float* W_ih    = (const float*)d_in[1];
    const float* W_hh    = (const float*)d_in[2];
    const float* b_ih    = (const float*)d_in[3];
    const float* b_hh    = (const float*)d_in[4];
    float* out = (float*)d_out;

    rnn_xproj_kernel<<<N_CTAS, THREADS>>>(feature, W_ih, b_ih, b_hh);
    rnn_recur_kernel<<<N_CTAS, THREADS>>>(W_hh, out);
}

// round 15
// speedup vs baseline: 2.4217x; 1.4028x over previous
#include <cuda_runtime.h>
#include <cstdint>

// Single-pass RNN. h_t = tanh(x_t @ W_ih^T + b_ih + b_hh + h_{t-1} @ W_hh^T)
// out = h_{T-1}.  B=4096, T=512, IN=15, HID=20.
//
// = R11 (zero-smem, all-shfl exchange) + R13-proven static FIFO fix.
// R14 trapped (misaligned address): the in-loop refill used LDG.64 at
// element offset (t+4)*15 + 2*tl, which is odd for odd t+4 -> only 4B
// aligned. Fixed: refill uses two scalar LDG.32 (same as R11's loader).
//
// x FIFO: 4-slot array indexed by (t&3) under unroll 4 — slot consumed at
// step t, refilled for t+4 -> full ~577cyc DRAM cover, no register moves.
// Warp = 3 batches x 10 lanes; lane owns units (2tl, 2tl+1), h in registers,
// x and h distributed by shfl64. No smem, no barriers. MUFU.TANH.

#define T_STEPS 512
#define BATCH   4096
#define N_IN    15
#define N_HID   20
#define BPW     3
#define THREADS 32
#define N_CTAS  ((BATCH + BPW - 1) / BPW)   // 1366
#define FULL    0xffffffffu

typedef unsigned long long ull;

__device__ __forceinline__ ull pack2(float lo, float hi) {
    ull r; asm("mov.b64 %0, {%1, %2};" : "=l"(r) : "f"(lo), "f"(hi)); return r;
}
__device__ __forceinline__ ull fma2(ull a, ull b, ull c) {
    ull d; asm("fma.rn.f32x2 %0, %1, %2, %3;" : "=l"(d) : "l"(a), "l"(b), "l"(c)); return d;
}
__device__ __forceinline__ ull add2(ull a, ull b) {
    ull d; asm("add.rn.f32x2 %0, %1, %2;" : "=l"(d) : "l"(a), "l"(b)); return d;
}
__device__ __forceinline__ float hsum2(ull a) {
    float lo, hi; asm("mov.b64 {%0, %1}, %2;" : "=f"(lo), "=f"(hi) : "l"(a));
    return lo + hi;
}
__device__ __forceinline__ float tanh_mufu(float z) {
    float r; asm("tanh.approx.f32 %0, %1;" : "=f"(r) : "f"(z)); return r;
}

__global__ __launch_bounds__(THREADS, 10)
void rnn_fused_fifo_kernel(const float* __restrict__ feature,
                           const float* __restrict__ W_ih,
                           const float* __restrict__ W_hh,
                           const float* __restrict__ b_ih,
                           const float* __restrict__ b_hh,
                           float* __restrict__ out)
{
    const int lane = threadIdx.x & 31;
    const int g    = lane / 10;                  // 0..2 batch slot (3 = riders)
    const int tl   = lane % 10;
    const bool active = (g < BPW);
    const int  gc  = active ? g : 0;
    const int  base = gc * 10;                   // first lane of this group
    const int  b   = blockIdx.x * BPW + gc;
    const bool valid = active && (b < BATCH);
    const int j0 = 2 * tl, j1 = 2 * tl + 1;

    // x-loader role: lane tl<8 supplies packed pair (x[2tl], x[2tl+1])
    const bool xl  = valid && (tl < 8);
    const bool xhi = (tl < 7);                   // pair 7 = (x14, 0)

    // ---- loop-invariant packed weights (f32x2 k-pairs) ----
    ull wx0[8], wx1[8], wh0[10], wh1[10];
#pragma unroll
    for (int p = 0; p < 7; p++) {
        wx0[p] = pack2(W_ih[j0 * N_IN + 2 * p], W_ih[j0 * N_IN + 2 * p + 1]);
        wx1[p] = pack2(W_ih[j1 * N_IN + 2 * p], W_ih[j1 * N_IN + 2 * p + 1]);
    }
    wx0[7] = pack2(W_ih[j0 * N_IN + 14], 0.0f);
    wx1[7] = pack2(W_ih[j1 * N_IN + 14], 0.0f);
#pragma unroll
    for (int p = 0; p < 10; p++) {
        wh0[p] = pack2(W_hh[j0 * N_HID + 2 * p], W_hh[j0 * N_HID + 2 * p + 1]);
        wh1[p] = pack2(W_hh[j1 * N_HID + 2 * p], W_hh[j1 * N_HID + 2 * p + 1]);
    }
    const ull bias2_0 = pack2(b_ih[j0] + b_hh[j0], 0.0f);
    const ull bias2_1 = pack2(b_ih[j1] + b_hh[j1], 0.0f);

    // ---- 4-slot x FIFO, statically indexed: slot q holds x_t with t&3==q ----
    const float* xrow = feature + (size_t)(valid ? b : 0) * T_STEPS * N_IN;
    ull fx[4];
#pragma unroll
    for (int q = 0; q < 4; q++)
        fx[q] = xl ? pack2(xrow[q * N_IN + 2 * tl],
                           xhi ? xrow[q * N_IN + 2 * tl + 1] : 0.0f) : 0ull;

    ull hpk = 0ull;   // packed (h[2tl], h[2tl+1]) — h never leaves registers

#pragma unroll 4
    for (int t = 0; t < T_STEPS; t++) {
        const int q = t & 3;

        // distribute x_t pairs from loader lanes (consume slot q this step)
        ull xp[8];
#pragma unroll
        for (int p = 0; p < 8; p++)
            xp[p] = __shfl_sync(FULL, fx[q], base + p);

        // refill slot q for t+4 with two scalar LDG.32 (4B-aligned only —
        // element offset (t+4)*15+2*tl can be odd, LDG.64 would trap);
        // first re-read at t+4 => full DRAM-latency cover
        if (xl && (t + 4) < T_STEPS) {
            const float* r4 = xrow + (t + 4) * N_IN + 2 * tl;
            fx[q] = pack2(r4[0], xhi ? r4[1] : 0.0f);
        }

        // gather h_{t-1} pairs: 10x shfl64 (packed, no pack instructions)
        ull hp[10];
#pragma unroll
        for (int s = 0; s < 10; s++)
            hp[s] = __shfl_sync(FULL, hpk, base + s);

        // 36 fma2 over 4 independent chains (depth ~9)
        ull a0 = bias2_0, c0 = 0ull, a1 = bias2_1, c1 = 0ull;
#pragma unroll
        for (int k = 0; k < 8; k++) {
            if (k & 1) { c0 = fma2(xp[k], wx0[k], c0); c1 = fma2(xp[k], wx1[k], c1); }
            else       { a0 = fma2(xp[k], wx0[k], a0); a1 = fma2(xp[k], wx1[k], a1); }
        }
#pragma unroll
        for (int k = 0; k < 10; k++) {
            if (k & 1) { c0 = fma2(hp[k], wh0[k], c0); c1 = fma2(hp[k], wh1[k], c1); }
            else       { a0 = fma2(hp[k], wh0[k], a0); a1 = fma2(hp[k], wh1[k], a1); }
        }
        const float z0 = hsum2(add2(a0, c0));
        const float z1 = hsum2(add2(a1, c1));

        hpk = pack2(tanh_mufu(z0), tanh_mufu(z1));
    }

    if (valid) {
        float lo, hi;
        asm("mov.b64 {%0, %1}, %2;" : "=f"(lo), "=f"(hi) : "l"(hpk));
        *(float2*)&out[b * N_HID + j0] = make_float2(lo, hi);  // 8B-aligned STG.64
    }
}

extern "C" void kernel_launch(void* const* d_in, const int* in_sizes, int n_in,
                              void* d_out, int out_size)
{
    const float* feature = (const float*)d_in[0];
    const float* W_ih    = (const float*)d_in[1];
    const float* W_hh    = (const float*)d_in[2];
    const float* b_ih    = (const float*)d_in[3];
    const float* b_hh    = (const float*)d_in[4];
    float* out = (float*)d_out;

    rnn_fused_fifo_kernel<<<N_CTAS, THREADS>>>(feature, W_ih, W_hh, b_ih, b_hh, out);
}